// round 2
// baseline (speedup 1.0000x reference)
#include <cuda_runtime.h>
#include <math.h>

#define N_NODES 50000
#define N_EDGES 800000
#define IN_CH   128
#define OUT_CH  64
#define BN_EPS  1e-5f

// ---------------- scratch (no allocation allowed) ----------------
__device__ float g_h[N_NODES * OUT_CH];      // x @ W
__device__ float g_agg[N_NODES * OUT_CH];    // aggregated messages
__device__ int   g_deg[N_NODES];
__device__ float g_dinv[N_NODES];
__device__ float g_sum[OUT_CH];
__device__ float g_sumsq[OUT_CH];
__device__ int   g_eidx[2 * N_EDGES];        // decoded int32 edges (src then dst)
__device__ int   g_is64;

// ---------------- edge dtype sniff + decode ----------------
// If edge_index is int64 (little-endian), every odd 32-bit word is 0
// (values are in [0, 50000)). If int32, odd words are edge indices (~never 0).
__global__ void k_sniff(const unsigned int* __restrict__ w) {
    if (threadIdx.x == 0 && blockIdx.x == 0) {
        int odd_zero = 1;
        #pragma unroll
        for (int i = 0; i < 16; i++)
            if (w[2 * i + 1] != 0u) odd_zero = 0;
        g_is64 = odd_zero;
    }
}

__global__ void k_decode(const unsigned int* __restrict__ w) {
    int i = blockIdx.x * blockDim.x + threadIdx.x;
    if (i >= 2 * N_EDGES) return;
    int is64 = g_is64;
    g_eidx[i] = (int)(is64 ? w[2 * (size_t)i] : w[i]);
}

// ---------------- init: deg = 1 (self loop), stats = 0 ----------------
__global__ void k_init() {
    int i = blockIdx.x * blockDim.x + threadIdx.x;
    if (i < N_NODES) g_deg[i] = 1;
    if (i < OUT_CH) { g_sum[i] = 0.f; g_sumsq[i] = 0.f; }
}

// ---------------- in-degree over dst ----------------
__global__ void k_deg() {
    int i = blockIdx.x * blockDim.x + threadIdx.x;
    if (i < N_EDGES) atomicAdd(&g_deg[g_eidx[N_EDGES + i]], 1);
}

__global__ void k_dinv() {
    int i = blockIdx.x * blockDim.x + threadIdx.x;
    if (i < N_NODES) g_dinv[i] = rsqrtf((float)g_deg[i]);
}

// ---------------- GEMM: h[N,64] = x[N,128] @ W[128,64] ----------------
// 64-row tile per block, 256 threads, 4x4 register blocking.
__global__ void __launch_bounds__(256) k_gemm(const float* __restrict__ x,
                                              const float* __restrict__ W) {
    __shared__ float As[64][128];   // x tile
    __shared__ float Ws[128][64];   // full W
    const int tid  = threadIdx.x;
    const int row0 = blockIdx.x * 64;

    // load W (8192 floats) as float4
    for (int i = tid; i < (IN_CH * OUT_CH) / 4; i += 256)
        ((float4*)Ws)[i] = ((const float4*)W)[i];

    // load x tile (64 x 128) as float4, zero-fill OOB rows
    for (int i = tid; i < (64 * IN_CH) / 4; i += 256) {
        int lin = i * 4;
        int r = lin / IN_CH, c = lin % IN_CH;
        int gr = row0 + r;
        float4 v = make_float4(0.f, 0.f, 0.f, 0.f);
        if (gr < N_NODES)
            v = *((const float4*)(x + (size_t)gr * IN_CH + c));
        *((float4*)&As[r][c]) = v;
    }
    __syncthreads();

    const int ty = tid >> 4;       // 0..15 -> rows ty*4..ty*4+3
    const int tx = tid & 15;       // 0..15 -> cols tx*4..tx*4+3
    float acc[4][4] = {};

    #pragma unroll 4
    for (int k = 0; k < IN_CH; k++) {
        float a0 = As[ty * 4 + 0][k];
        float a1 = As[ty * 4 + 1][k];
        float a2 = As[ty * 4 + 2][k];
        float a3 = As[ty * 4 + 3][k];
        float4 b = *((const float4*)&Ws[k][tx * 4]);
        acc[0][0] += a0 * b.x; acc[0][1] += a0 * b.y; acc[0][2] += a0 * b.z; acc[0][3] += a0 * b.w;
        acc[1][0] += a1 * b.x; acc[1][1] += a1 * b.y; acc[1][2] += a1 * b.z; acc[1][3] += a1 * b.w;
        acc[2][0] += a2 * b.x; acc[2][1] += a2 * b.y; acc[2][2] += a2 * b.z; acc[2][3] += a2 * b.w;
        acc[3][0] += a3 * b.x; acc[3][1] += a3 * b.y; acc[3][2] += a3 * b.z; acc[3][3] += a3 * b.w;
    }

    #pragma unroll
    for (int i = 0; i < 4; i++) {
        int r = row0 + ty * 4 + i;
        if (r < N_NODES) {
            float4 v = make_float4(acc[i][0], acc[i][1], acc[i][2], acc[i][3]);
            *((float4*)&g_h[(size_t)r * OUT_CH + tx * 4]) = v;
        }
    }
}

// ---------------- agg init with self-loop contribution ----------------
__global__ void k_self() {
    int t = blockIdx.x * blockDim.x + threadIdx.x;
    if (t >= N_NODES * 16) return;
    int n = t >> 4, q = t & 15;
    float s = g_dinv[n]; s = s * s;   // norm for self loop
    float4 v = *((const float4*)&g_h[(size_t)n * OUT_CH + q * 4]);
    v.x *= s; v.y *= s; v.z *= s; v.w *= s;
    *((float4*)&g_agg[(size_t)n * OUT_CH + q * 4]) = v;
}

// ---------------- edge scatter: 16 threads / edge, v4 red ----------------
__global__ void __launch_bounds__(256) k_scatter() {
    long long t = (long long)blockIdx.x * blockDim.x + threadIdx.x;
    if (t >= (long long)N_EDGES * 16) return;
    int e = (int)(t >> 4), q = (int)(t & 15);
    int s = g_eidx[e];
    int d = g_eidx[N_EDGES + e];
    float norm = g_dinv[s] * g_dinv[d];
    float4 v = *((const float4*)&g_h[(size_t)s * OUT_CH + q * 4]);
    float* p = &g_agg[(size_t)d * OUT_CH + q * 4];
    asm volatile("red.global.add.v4.f32 [%0], {%1,%2,%3,%4};"
                 :: "l"(p), "f"(v.x * norm), "f"(v.y * norm),
                    "f"(v.z * norm), "f"(v.w * norm)
                 : "memory");
}

// ---------------- tanh(agg + bias) -> out; accumulate per-channel stats ----
// Grid stride is a multiple of 64, so channel = tid & 63 is loop-invariant.
__global__ void __launch_bounds__(256) k_act(const float* __restrict__ bias,
                                             float* __restrict__ out) {
    const int tid = threadIdx.x;
    const int c = tid & 63;
    const float b = bias[c];
    float s = 0.f, s2 = 0.f;
    const long long total  = (long long)N_NODES * OUT_CH;
    const long long stride = (long long)gridDim.x * blockDim.x;   // 131072 (mult of 64)
    for (long long i = (long long)blockIdx.x * blockDim.x + tid; i < total; i += stride) {
        float v = tanhf(g_agg[i] + b);
        out[i] = v;
        s += v; s2 += v * v;
    }
    __shared__ float sh[256];
    sh[tid] = s; __syncthreads();
    if (tid < 64) atomicAdd(&g_sum[tid], sh[tid] + sh[tid + 64] + sh[tid + 128] + sh[tid + 192]);
    __syncthreads();
    sh[tid] = s2; __syncthreads();
    if (tid < 64) atomicAdd(&g_sumsq[tid], sh[tid] + sh[tid + 64] + sh[tid + 128] + sh[tid + 192]);
}

// ---------------- batchnorm (biased var), in-place on out ----------------
__global__ void __launch_bounds__(256) k_bn(const float* __restrict__ gamma,
                                            const float* __restrict__ beta,
                                            float* __restrict__ out) {
    const int tid = threadIdx.x;
    const int c = tid & 63;
    const float invN = 1.0f / (float)N_NODES;
    const float mean = g_sum[c] * invN;
    const float var  = g_sumsq[c] * invN - mean * mean;
    const float scale = gamma[c] * rsqrtf(var + BN_EPS);
    const float shift = beta[c] - mean * scale;
    const long long total  = (long long)N_NODES * OUT_CH;
    const long long stride = (long long)gridDim.x * blockDim.x;   // mult of 64
    for (long long i = (long long)blockIdx.x * blockDim.x + tid; i < total; i += stride)
        out[i] = out[i] * scale + shift;
}

// ---------------- launch ----------------
extern "C" void kernel_launch(void* const* d_in, const int* in_sizes, int n_in,
                              void* d_out, int out_size) {
    const float*        x     = (const float*)d_in[0];
    const unsigned int* ei    = (const unsigned int*)d_in[1];  // int32 or int64, sniffed
    const float*        W     = (const float*)d_in[2];
    const float*        bias  = (const float*)d_in[3];
    const float*        gamma = (const float*)d_in[4];
    const float*        beta  = (const float*)d_in[5];
    float*              out   = (float*)d_out;

    k_sniff<<<1, 32>>>(ei);
    k_decode<<<(2 * N_EDGES + 255) / 256, 256>>>(ei);
    k_init<<<(N_NODES + 255) / 256, 256>>>();
    k_deg<<<(N_EDGES + 255) / 256, 256>>>();
    k_dinv<<<(N_NODES + 255) / 256, 256>>>();
    k_gemm<<<(N_NODES + 63) / 64, 256>>>(x, W);
    k_self<<<(N_NODES * 16 + 255) / 256, 256>>>();
    k_scatter<<<(int)(((long long)N_EDGES * 16 + 255) / 256), 256>>>();
    k_act<<<512, 256>>>(bias, out);
    k_bn<<<512, 256>>>(gamma, beta, out);
}

// round 4
// speedup vs baseline: 1.0420x; 1.0420x over previous
#include <cuda_runtime.h>
#include <math.h>

#define N_NODES 50000
#define N_EDGES 800000
#define IN_CH   128
#define OUT_CH  64
#define BN_EPS  1e-5f

// ---------------- scratch (no allocation allowed) ----------------
__device__ float g_h[N_NODES * OUT_CH];      // x @ W
__device__ float g_agg[N_NODES * OUT_CH];    // aggregated messages (edges only)
__device__ int   g_deg[N_NODES];
__device__ float g_dinv[N_NODES];
__device__ float g_sum[OUT_CH];
__device__ float g_sumsq[OUT_CH];
__device__ int   g_eidx[2 * N_EDGES];        // decoded int32 edges (src then dst)
__device__ int   g_is64;

// ---------------- edge dtype sniff ----------------
// If edge_index is int64 (little-endian), every odd 32-bit word is 0
// (values < 50000). If int32, odd words are edge indices (~never all 0).
__global__ void k_sniff(const unsigned int* __restrict__ w) {
    if (threadIdx.x == 0 && blockIdx.x == 0) {
        int odd_zero = 1;
        #pragma unroll
        for (int i = 0; i < 16; i++)
            if (w[2 * i + 1] != 0u) odd_zero = 0;
        g_is64 = odd_zero;
    }
}

// ---------------- init: deg = 1 (self loop), stats = 0 ----------------
__global__ void k_init() {
    int i = blockIdx.x * blockDim.x + threadIdx.x;
    if (i < N_NODES) g_deg[i] = 1;
    if (i < OUT_CH) { g_sum[i] = 0.f; g_sumsq[i] = 0.f; }
}

// ---------------- fused decode + in-degree ----------------
__global__ void k_decode_deg(const unsigned int* __restrict__ w) {
    int i = blockIdx.x * blockDim.x + threadIdx.x;
    if (i >= 2 * N_EDGES) return;
    int is64 = g_is64;
    int v = (int)(is64 ? w[2 * (size_t)i] : w[i]);
    g_eidx[i] = v;
    if (i >= N_EDGES) atomicAdd(&g_deg[v], 1);   // dst half
}

__global__ void k_dinv() {
    int i = blockIdx.x * blockDim.x + threadIdx.x;
    if (i < N_NODES) g_dinv[i] = rsqrtf((float)g_deg[i]);
}

// ---------------- zero g_agg (scatter accumulates into it) ----------------
__global__ void k_zero() {
    int i = blockIdx.x * blockDim.x + threadIdx.x;
    if (i < N_NODES * 16)
        ((float4*)g_agg)[i] = make_float4(0.f, 0.f, 0.f, 0.f);
}

// ---------------- GEMM: h[N,64] = x[N,128] @ W[128,64] ----------------
__global__ void __launch_bounds__(256) k_gemm(const float* __restrict__ x,
                                              const float* __restrict__ W) {
    __shared__ float As[64][128];
    __shared__ float Ws[128][64];
    const int tid  = threadIdx.x;
    const int row0 = blockIdx.x * 64;

    for (int i = tid; i < (IN_CH * OUT_CH) / 4; i += 256)
        ((float4*)Ws)[i] = ((const float4*)W)[i];

    for (int i = tid; i < (64 * IN_CH) / 4; i += 256) {
        int lin = i * 4;
        int r = lin / IN_CH, c = lin % IN_CH;
        int gr = row0 + r;
        float4 v = make_float4(0.f, 0.f, 0.f, 0.f);
        if (gr < N_NODES)
            v = *((const float4*)(x + (size_t)gr * IN_CH + c));
        *((float4*)&As[r][c]) = v;
    }
    __syncthreads();

    const int ty = tid >> 4;
    const int tx = tid & 15;
    float acc[4][4] = {};

    #pragma unroll 4
    for (int k = 0; k < IN_CH; k++) {
        float a0 = As[ty * 4 + 0][k];
        float a1 = As[ty * 4 + 1][k];
        float a2 = As[ty * 4 + 2][k];
        float a3 = As[ty * 4 + 3][k];
        float4 b = *((const float4*)&Ws[k][tx * 4]);
        acc[0][0] += a0 * b.x; acc[0][1] += a0 * b.y; acc[0][2] += a0 * b.z; acc[0][3] += a0 * b.w;
        acc[1][0] += a1 * b.x; acc[1][1] += a1 * b.y; acc[1][2] += a1 * b.z; acc[1][3] += a1 * b.w;
        acc[2][0] += a2 * b.x; acc[2][1] += a2 * b.y; acc[2][2] += a2 * b.z; acc[2][3] += a2 * b.w;
        acc[3][0] += a3 * b.x; acc[3][1] += a3 * b.y; acc[3][2] += a3 * b.z; acc[3][3] += a3 * b.w;
    }

    #pragma unroll
    for (int i = 0; i < 4; i++) {
        int r = row0 + ty * 4 + i;
        if (r < N_NODES) {
            float4 v = make_float4(acc[i][0], acc[i][1], acc[i][2], acc[i][3]);
            *((float4*)&g_h[(size_t)r * OUT_CH + tx * 4]) = v;
        }
    }
}

// ---------------- edge scatter: 16 threads / edge, v4 red ----------------
__global__ void __launch_bounds__(256) k_scatter() {
    long long t = (long long)blockIdx.x * blockDim.x + threadIdx.x;
    if (t >= (long long)N_EDGES * 16) return;
    int e = (int)(t >> 4), q = (int)(t & 15);
    int s = g_eidx[e];
    int d = g_eidx[N_EDGES + e];
    float norm = g_dinv[s] * g_dinv[d];
    float4 v = *((const float4*)&g_h[(size_t)s * OUT_CH + q * 4]);
    float* p = &g_agg[(size_t)d * OUT_CH + q * 4];
    asm volatile("red.global.add.v4.f32 [%0], {%1,%2,%3,%4};"
                 :: "l"(p), "f"(v.x * norm), "f"(v.y * norm),
                    "f"(v.z * norm), "f"(v.w * norm)
                 : "memory");
}

// --------- act: out = tanh(agg + dinv^2*h + bias), fused self-loop + stats ---------
// Grid*block is a multiple of 16 float4s -> channel group (i & 15) is loop-invariant.
__global__ void __launch_bounds__(256) k_act(const float* __restrict__ bias,
                                             float* __restrict__ out) {
    const int tid = threadIdx.x;
    const int cg = tid & 15;                       // float4 channel group 0..15
    const float4 b4 = ((const float4*)bias)[cg];
    float4 s  = make_float4(0.f, 0.f, 0.f, 0.f);
    float4 s2 = make_float4(0.f, 0.f, 0.f, 0.f);
    const int total4 = N_NODES * 16;
    const int stride = gridDim.x * blockDim.x;     // 131072, multiple of 16
    for (int i = blockIdx.x * blockDim.x + tid; i < total4; i += stride) {
        int n = i >> 4;
        float di = g_dinv[n];
        float sl = di * di;
        float4 a = ((const float4*)g_agg)[i];
        float4 h = ((const float4*)g_h)[i];
        float4 v;
        v.x = tanhf(a.x + sl * h.x + b4.x);
        v.y = tanhf(a.y + sl * h.y + b4.y);
        v.z = tanhf(a.z + sl * h.z + b4.z);
        v.w = tanhf(a.w + sl * h.w + b4.w);
        ((float4*)out)[i] = v;
        s.x += v.x; s.y += v.y; s.z += v.z; s.w += v.w;
        s2.x += v.x * v.x; s2.y += v.y * v.y; s2.z += v.z * v.z; s2.w += v.w * v.w;
    }
    __shared__ float4 sh[256];
    sh[tid] = s; __syncthreads();
    if (tid < 16) {
        float4 acc = sh[tid];
        #pragma unroll
        for (int j = 1; j < 16; j++) {
            float4 o = sh[tid + 16 * j];
            acc.x += o.x; acc.y += o.y; acc.z += o.z; acc.w += o.w;
        }
        atomicAdd(&g_sum[cg * 4 + 0], acc.x);
        atomicAdd(&g_sum[cg * 4 + 1], acc.y);
        atomicAdd(&g_sum[cg * 4 + 2], acc.z);
        atomicAdd(&g_sum[cg * 4 + 3], acc.w);
    }
    __syncthreads();
    sh[tid] = s2; __syncthreads();
    if (tid < 16) {
        float4 acc = sh[tid];
        #pragma unroll
        for (int j = 1; j < 16; j++) {
            float4 o = sh[tid + 16 * j];
            acc.x += o.x; acc.y += o.y; acc.z += o.z; acc.w += o.w;
        }
        atomicAdd(&g_sumsq[cg * 4 + 0], acc.x);
        atomicAdd(&g_sumsq[cg * 4 + 1], acc.y);
        atomicAdd(&g_sumsq[cg * 4 + 2], acc.z);
        atomicAdd(&g_sumsq[cg * 4 + 3], acc.w);
    }
}

// ---------------- batchnorm (biased var), in-place on out ----------------
__global__ void __launch_bounds__(256) k_bn(const float* __restrict__ gamma,
                                            const float* __restrict__ beta,
                                            float* __restrict__ out) {
    const int tid = threadIdx.x;
    const int cg = tid & 15;
    const float4 g4 = ((const float4*)gamma)[cg];
    const float4 be4 = ((const float4*)beta)[cg];
    const float invN = 1.0f / (float)N_NODES;
    float4 sc, sf;
    {
        float4 su = ((const float4*)g_sum)[cg];
        float4 sq = ((const float4*)g_sumsq)[cg];
        float mx = su.x * invN, my = su.y * invN, mz = su.z * invN, mw = su.w * invN;
        sc.x = g4.x * rsqrtf(sq.x * invN - mx * mx + BN_EPS);
        sc.y = g4.y * rsqrtf(sq.y * invN - my * my + BN_EPS);
        sc.z = g4.z * rsqrtf(sq.z * invN - mz * mz + BN_EPS);
        sc.w = g4.w * rsqrtf(sq.w * invN - mw * mw + BN_EPS);
        sf.x = be4.x - mx * sc.x;
        sf.y = be4.y - my * sc.y;
        sf.z = be4.z - mz * sc.z;
        sf.w = be4.w - mw * sc.w;
    }
    const int total4 = N_NODES * 16;
    const int stride = gridDim.x * blockDim.x;
    for (int i = blockIdx.x * blockDim.x + tid; i < total4; i += stride) {
        float4 v = ((const float4*)out)[i];
        v.x = v.x * sc.x + sf.x;
        v.y = v.y * sc.y + sf.y;
        v.z = v.z * sc.z + sf.z;
        v.w = v.w * sc.w + sf.w;
        ((float4*)out)[i] = v;
    }
}

// ---------------- streams/events for fork-join (created once, no device mem) ----
static struct SideStream {
    cudaStream_t s;
    cudaEvent_t fork_ev, join_ev;
    SideStream() {
        cudaStreamCreateWithFlags(&s, cudaStreamNonBlocking);
        cudaEventCreateWithFlags(&fork_ev, cudaEventDisableTiming);
        cudaEventCreateWithFlags(&join_ev, cudaEventDisableTiming);
    }
} g_ss;

// ---------------- launch ----------------
extern "C" void kernel_launch(void* const* d_in, const int* in_sizes, int n_in,
                              void* d_out, int out_size) {
    const float*        x     = (const float*)d_in[0];
    const unsigned int* ei    = (const unsigned int*)d_in[1];  // int32 or int64, sniffed
    const float*        W     = (const float*)d_in[2];
    const float*        bias  = (const float*)d_in[3];
    const float*        gamma = (const float*)d_in[4];
    const float*        beta  = (const float*)d_in[5];
    float*              out   = (float*)d_out;

    // fork: edge chain on side stream, overlapped with zero+gemm on main stream
    cudaEventRecord(g_ss.fork_ev, 0);
    cudaStreamWaitEvent(g_ss.s, g_ss.fork_ev, 0);

    k_init<<<(N_NODES + 255) / 256, 256, 0, g_ss.s>>>();
    k_sniff<<<1, 32, 0, g_ss.s>>>(ei);
    k_decode_deg<<<(2 * N_EDGES + 255) / 256, 256, 0, g_ss.s>>>(ei);
    k_dinv<<<(N_NODES + 255) / 256, 256, 0, g_ss.s>>>();
    cudaEventRecord(g_ss.join_ev, g_ss.s);

    k_zero<<<(N_NODES * 16 + 255) / 256, 256>>>();
    k_gemm<<<(N_NODES + 63) / 64, 256>>>(x, W);

    // join, then scatter/act/bn on main stream
    cudaStreamWaitEvent(0, g_ss.join_ev, 0);
    k_scatter<<<(int)(((long long)N_EDGES * 16 + 255) / 256), 256>>>();
    k_act<<<512, 256>>>(bias, out);
    k_bn<<<512, 256>>>(gamma, beta, out);
}